// round 2
// baseline (speedup 1.0000x reference)
#include <cuda_runtime.h>
#include <math.h>

#define BATCH 8
#define SEQ 1370
#define DIM 1024
#define HEADS 16
#define HDIM 64
#define MROWS (BATCH * SEQ)   // 10960

typedef unsigned long long ull;

// Scratch (allocation-free: device globals)
__device__ float g_q[BATCH * HEADS * SEQ * HDIM];   // [B,H,S,Dh]
__device__ float g_k[BATCH * HEADS * SEQ * HDIM];
__device__ float g_v[BATCH * HEADS * SEQ * HDIM];
__device__ float g_ctx[BATCH * SEQ * DIM];          // [B,S,D]

// ---------------- packed f32x2 helpers ----------------
__device__ __forceinline__ ull pk2(float lo, float hi) {
    ull r; asm("mov.b64 %0, {%1, %2};" : "=l"(r) : "f"(lo), "f"(hi)); return r;
}
__device__ __forceinline__ void upk2(ull v, float& lo, float& hi) {
    asm("mov.b64 {%0, %1}, %2;" : "=f"(lo), "=f"(hi) : "l"(v));
}
__device__ __forceinline__ void fma2(ull& d, ull a, ull b) {
    asm("fma.rn.f32x2 %0, %1, %2, %3;" : "=l"(d) : "l"(a), "l"(b), "l"(d));
}
__device__ __forceinline__ ull mul2(ull a, ull b) {
    ull r; asm("mul.rn.f32x2 %0, %1, %2;" : "=l"(r) : "l"(a), "l"(b)); return r;
}

// ---------------------------------------------------------------------------
// GEMM: C[M,1024] = A[M,1024] @ W[1024,1024] + bias
// 128x128 tile, BK=16, 256 threads, 8x8 per thread, f32x2 inner loop,
// register-prefetch pipeline.
// csel 0/1/2 -> g_q/g_k/g_v ([B,H,S,Dh]); 3 -> Cext [M,N]. asel 1 -> g_ctx.
// ---------------------------------------------------------------------------
__global__ __launch_bounds__(256, 2) void gemm_kernel(
    const float* __restrict__ Aext, const float* __restrict__ W,
    const float* __restrict__ bias, float* __restrict__ Cext,
    int asel, int csel)
{
    __shared__ float As[128][20];   // pad 20 for conflict-free strided stores
    __shared__ float Bs[16][128];

    const float* A = (asel == 1) ? g_ctx : Aext;

    int tid = threadIdx.x;
    int tx = tid & 15;
    int ty = tid >> 4;
    int m0 = blockIdx.x * 128;
    int n0 = blockIdx.y * 128;

    // A load mapping: thread -> row m0+am, k offsets ak, ak+4
    int am = tid >> 1;
    int ak = (tid & 1) * 8;
    bool aval = (m0 + am) < MROWS;
    const float* Ap = A + (size_t)(m0 + am) * DIM + ak;
    // B load mapping: W row bk, cols bn and bn+64
    int bk = tid >> 4;
    int bn = (tid & 15) * 4;
    const float* Bp = W + (size_t)bk * DIM + n0 + bn;

    ull acc[8][4];
#pragma unroll
    for (int i = 0; i < 8; i++)
#pragma unroll
        for (int j = 0; j < 4; j++) acc[i][j] = 0ull;

    float4 ra0, ra1, rb0, rb1;
    const float4 z4 = make_float4(0.f, 0.f, 0.f, 0.f);

    // preload tile 0
    ra0 = aval ? *(const float4*)(Ap)     : z4;
    ra1 = aval ? *(const float4*)(Ap + 4) : z4;
    rb0 = *(const float4*)(Bp);
    rb1 = *(const float4*)(Bp + 64);

    for (int t = 0; t < 64; t++) {
        __syncthreads();
        *(float4*)&As[am][ak]     = ra0;
        *(float4*)&As[am][ak + 4] = ra1;
        *(float4*)&Bs[bk][bn]      = rb0;
        *(float4*)&Bs[bk][bn + 64] = rb1;
        __syncthreads();

        if (t < 63) {
            const float* Ap2 = Ap + (t + 1) * 16;
            ra0 = aval ? *(const float4*)(Ap2)     : z4;
            ra1 = aval ? *(const float4*)(Ap2 + 4) : z4;
            const float* Bp2 = Bp + (size_t)(t + 1) * 16 * DIM;
            rb0 = *(const float4*)(Bp2);
            rb1 = *(const float4*)(Bp2 + 64);
        }

#pragma unroll
        for (int k = 0; k < 16; k++) {
            ull b2[4];
            float4 bv0 = *(float4*)&Bs[k][tx * 8];
            float4 bv1 = *(float4*)&Bs[k][tx * 8 + 4];
            b2[0] = pk2(bv0.x, bv0.y);
            b2[1] = pk2(bv0.z, bv0.w);
            b2[2] = pk2(bv1.x, bv1.y);
            b2[3] = pk2(bv1.z, bv1.w);
#pragma unroll
            for (int i = 0; i < 8; i++) {
                float av = As[ty * 8 + i][k];
                ull a2 = pk2(av, av);
#pragma unroll
                for (int j = 0; j < 4; j++) fma2(acc[i][j], a2, b2[j]);
            }
        }
    }

    // Epilogue
#pragma unroll
    for (int i = 0; i < 8; i++) {
        int m = m0 + ty * 8 + i;
        if (m >= MROWS) continue;
        int b_idx = m / SEQ;
        int s_idx = m - b_idx * SEQ;
#pragma unroll
        for (int j2 = 0; j2 < 4; j2++) {
            float v0, v1;
            upk2(acc[i][j2], v0, v1);
            int n = n0 + tx * 8 + j2 * 2;
            v0 += bias[n];
            v1 += bias[n + 1];
            if (csel <= 2) {
                float* dst = (csel == 0) ? g_q : (csel == 1) ? g_k : g_v;
                int h = n >> 6;
                int d = n & 63;
                size_t base = (((size_t)(b_idx * HEADS + h)) * SEQ + s_idx) * HDIM + d;
                dst[base] = v0;
                dst[base + 1] = v1;  // same head: d<63 since n even, d+1<=63
            } else {
                Cext[(size_t)m * DIM + n] = v0;
                Cext[(size_t)m * DIM + n + 1] = v1;
            }
        }
    }
}

// ---------------------------------------------------------------------------
// Flash attention, 64 q-rows x 64 k-cols tiles, f32x2 + float4-LDS.
// Thread (tx,ty): q rows ty*4+i ; S k-cols tx+16j ; O cols tx*4+j.
// ---------------------------------------------------------------------------
#define AST 68  // smem row stride (floats): 68*4=272 bytes, 16B aligned

__global__ __launch_bounds__(256, 2) void attn_kernel()
{
    extern __shared__ float sm[];
    float* Qs = sm;                // [64][68]
    float* Ks = sm + 64 * AST;     // [64][68]
    float* Vs = sm + 2 * 64 * AST; // [64][68]
    float* Ps = sm + 3 * 64 * AST; // [64][68]

    int tid = threadIdx.x;
    int tx = tid & 15;
    int ty = tid >> 4;
    int bh = blockIdx.y;
    int b = bh >> 4;
    int h = bh & 15;
    int q0 = blockIdx.x * 64;

    const float* Qg = g_q + ((size_t)(b * HEADS + h)) * SEQ * HDIM;
    const float* Kg = g_k + ((size_t)(b * HEADS + h)) * SEQ * HDIM;
    const float* Vg = g_v + ((size_t)(b * HEADS + h)) * SEQ * HDIM;

    const float4 z4 = make_float4(0.f, 0.f, 0.f, 0.f);

    // Load Q tile
    for (int e = tid; e < 64 * 16; e += 256) {
        int r = e >> 4;
        int d4 = (e & 15) * 4;
        float4 v = (q0 + r < SEQ) ? *(const float4*)(Qg + (size_t)(q0 + r) * HDIM + d4) : z4;
        *(float4*)&Qs[r * AST + d4] = v;
    }

    float m_i[4], l_i[4];
    ull o2[4][2];
#pragma unroll
    for (int i = 0; i < 4; i++) {
        m_i[i] = -INFINITY;
        l_i[i] = 0.f;
        o2[i][0] = 0ull;
        o2[i][1] = 0ull;
    }

    const float scale = 0.125f;  // 1/sqrt(64)

    for (int k0 = 0; k0 < SEQ; k0 += 64) {
        __syncthreads();  // prev PV done reading Ks/Vs/Ps
        for (int e = tid; e < 64 * 16; e += 256) {
            int r = e >> 4;
            int d4 = (e & 15) * 4;
            float4 kv = z4, vv = z4;
            if (k0 + r < SEQ) {
                kv = *(const float4*)(Kg + (size_t)(k0 + r) * HDIM + d4);
                vv = *(const float4*)(Vg + (size_t)(k0 + r) * HDIM + d4);
            }
            *(float4*)&Ks[r * AST + d4] = kv;
            *(float4*)&Vs[r * AST + d4] = vv;
        }
        __syncthreads();

        // S = Q @ K^T  (d-vectorized packed dot products)
        ull sacc[4][4];
#pragma unroll
        for (int i = 0; i < 4; i++)
#pragma unroll
            for (int j = 0; j < 4; j++) sacc[i][j] = 0ull;

#pragma unroll
        for (int d4 = 0; d4 < 64; d4 += 4) {
            ull q2[4][2], k2[4][2];
#pragma unroll
            for (int i = 0; i < 4; i++) {
                float4 qv = *(float4*)&Qs[(ty * 4 + i) * AST + d4];
                q2[i][0] = pk2(qv.x, qv.y);
                q2[i][1] = pk2(qv.z, qv.w);
            }
#pragma unroll
            for (int j = 0; j < 4; j++) {
                float4 kv = *(float4*)&Ks[(tx + 16 * j) * AST + d4];
                k2[j][0] = pk2(kv.x, kv.y);
                k2[j][1] = pk2(kv.z, kv.w);
            }
#pragma unroll
            for (int i = 0; i < 4; i++)
#pragma unroll
                for (int j = 0; j < 4; j++) {
                    fma2(sacc[i][j], q2[i][0], k2[j][0]);
                    fma2(sacc[i][j], q2[i][1], k2[j][1]);
                }
        }

        float s[4][4];
#pragma unroll
        for (int i = 0; i < 4; i++)
#pragma unroll
            for (int j = 0; j < 4; j++) {
                float lo, hi;
                upk2(sacc[i][j], lo, hi);
                bool valid = (k0 + tx + 16 * j) < SEQ;
                s[i][j] = valid ? (lo + hi) * scale : -INFINITY;
            }

        // Online softmax (rows owned by 16 tx-lanes)
#pragma unroll
        for (int i = 0; i < 4; i++) {
            float rmax = fmaxf(fmaxf(s[i][0], s[i][1]), fmaxf(s[i][2], s[i][3]));
#pragma unroll
            for (int off = 8; off >= 1; off >>= 1)
                rmax = fmaxf(rmax, __shfl_xor_sync(0xffffffffu, rmax, off, 16));

            float mn = fmaxf(m_i[i], rmax);
            float alpha = __expf(m_i[i] - mn);
            m_i[i] = mn;

            float rsum = 0.f;
#pragma unroll
            for (int j = 0; j < 4; j++) {
                float p = __expf(s[i][j] - mn);
                s[i][j] = p;
                rsum += p;
            }
#pragma unroll
            for (int off = 8; off >= 1; off >>= 1)
                rsum += __shfl_xor_sync(0xffffffffu, rsum, off, 16);

            l_i[i] = l_i[i] * alpha + rsum;
            ull a2 = pk2(alpha, alpha);
            o2[i][0] = mul2(o2[i][0], a2);
            o2[i][1] = mul2(o2[i][1], a2);
#pragma unroll
            for (int j = 0; j < 4; j++)
                Ps[(ty * 4 + i) * AST + tx + 16 * j] = s[i][j];
        }
        __syncthreads();

        // O += P @ V  (n-vectorized outer product)
#pragma unroll 4
        for (int kk = 0; kk < 64; kk++) {
            float4 vv = *(float4*)&Vs[kk * AST + tx * 4];
            ull v20 = pk2(vv.x, vv.y);
            ull v21 = pk2(vv.z, vv.w);
#pragma unroll
            for (int i = 0; i < 4; i++) {
                float p = Ps[(ty * 4 + i) * AST + kk];
                ull p2 = pk2(p, p);
                fma2(o2[i][0], p2, v20);
                fma2(o2[i][1], p2, v21);
            }
        }
    }

    // Epilogue: normalize, write [B,S,D]
#pragma unroll
    for (int i = 0; i < 4; i++) {
        int q = q0 + ty * 4 + i;
        if (q >= SEQ) continue;
        float inv = 1.f / l_i[i];
        float a, bq_, c, d;
        upk2(o2[i][0], a, bq_);
        upk2(o2[i][1], c, d);
        float4 ov = make_float4(a * inv, bq_ * inv, c * inv, d * inv);
        *(float4*)&g_ctx[((size_t)(b * SEQ + q)) * DIM + h * HDIM + tx * 4] = ov;
    }
}

// ---------------------------------------------------------------------------
extern "C" void kernel_launch(void* const* d_in, const int* in_sizes, int n_in,
                              void* d_out, int out_size)
{
    const float* x  = (const float*)d_in[0];
    const float* Wq = (const float*)d_in[1];
    const float* bq = (const float*)d_in[2];
    const float* Wk = (const float*)d_in[3];
    const float* bk = (const float*)d_in[4];
    const float* Wv = (const float*)d_in[5];
    const float* bv = (const float*)d_in[6];
    const float* Wo = (const float*)d_in[7];
    const float* bo = (const float*)d_in[8];
    float* out = (float*)d_out;

    dim3 gemmGrid((MROWS + 127) / 128, DIM / 128);  // 86 x 8

    gemm_kernel<<<gemmGrid, 256>>>(x, Wq, bq, nullptr, 0, 0);
    gemm_kernel<<<gemmGrid, 256>>>(x, Wk, bk, nullptr, 0, 1);
    gemm_kernel<<<gemmGrid, 256>>>(x, Wv, bv, nullptr, 0, 2);

    int smem = 4 * 64 * AST * sizeof(float);  // 69632
    cudaFuncSetAttribute(attn_kernel, cudaFuncAttributeMaxDynamicSharedMemorySize, smem);
    dim3 attnGrid((SEQ + 63) / 64, BATCH * HEADS);  // 22 x 128
    attn_kernel<<<attnGrid, 256, smem>>>();

    gemm_kernel<<<gemmGrid, 256>>>(nullptr, Wo, bo, out, 1, 3);
}

// round 3
// speedup vs baseline: 3.9660x; 3.9660x over previous
#include <cuda_runtime.h>
#include <math.h>
#include <stdint.h>

#define BATCH 8
#define SEQ 1370
#define DIM 1024
#define HEADS 16
#define HDIM 64
#define MROWS (BATCH * SEQ)   // 10960

// Scratch (allocation-free: device globals)
__device__ float g_q[BATCH * HEADS * SEQ * HDIM];   // [B,H,S,Dh]
__device__ float g_k[BATCH * HEADS * SEQ * HDIM];
__device__ float g_v[BATCH * HEADS * SEQ * HDIM];
__device__ float g_ctx[BATCH * SEQ * DIM];          // [B,S,D]

__device__ __forceinline__ float to_tf32(float x) {
    float r; asm("cvt.rna.tf32.f32 %0, %1;" : "=f"(r) : "f"(x)); return r;
}

__device__ __forceinline__ void mma_tf32(float c[4],
    unsigned a0, unsigned a1, unsigned a2, unsigned a3,
    unsigned b0, unsigned b1)
{
    asm volatile(
        "mma.sync.aligned.m16n8k8.row.col.f32.tf32.tf32.f32 "
        "{%0,%1,%2,%3}, {%4,%5,%6,%7}, {%8,%9}, {%0,%1,%2,%3};"
        : "+f"(c[0]), "+f"(c[1]), "+f"(c[2]), "+f"(c[3])
        : "r"(a0), "r"(a1), "r"(a2), "r"(a3), "r"(b0), "r"(b1));
}

__device__ __forceinline__ unsigned fu(float x) { return __float_as_uint(x); }

// ---------------------------------------------------------------------------
// TF32 GEMM: C[M,1024] = A[M,1024] @ W[1024,1024] + bias
// 128x128 tile, BK=16, 8 warps (2x4), warp tile 64x32, m16n8k8 tf32 MMA.
// csel 0/1/2 -> g_q/g_k/g_v ([B,H,S,Dh]); 3 -> Cext [M,N]. asel 1 -> g_ctx.
// ---------------------------------------------------------------------------
__device__ __forceinline__ void store_pair(int csel, float* __restrict__ Cext,
                                           int m, int n, float v0, float v1)
{
    if (m >= MROWS) return;
    if (csel <= 2) {
        float* dst = (csel == 0) ? g_q : (csel == 1) ? g_k : g_v;
        int b = m / SEQ;
        int s = m - b * SEQ;
        int h = n >> 6;
        int d = n & 63;
        *(float2*)&dst[(((size_t)(b * HEADS + h)) * SEQ + s) * HDIM + d] =
            make_float2(v0, v1);
    } else {
        *(float2*)&Cext[(size_t)m * DIM + n] = make_float2(v0, v1);
    }
}

__global__ __launch_bounds__(256) void gemm_tf32(
    const float* __restrict__ Aext, const float* __restrict__ W,
    const float* __restrict__ bias, float* __restrict__ Cext,
    int asel, int csel)
{
    __shared__ float As[128][20];   // stride 20: conflict-free A-frag loads
    __shared__ float Bs[16][136];   // stride 136: conflict-free B-frag loads

    const float* A = (asel == 1) ? g_ctx : Aext;

    int tid = threadIdx.x;
    int wid = tid >> 5, lane = tid & 31;
    int wm = wid & 1, wn = wid >> 1;
    int lr = lane >> 2, lc = lane & 3;
    int m0 = blockIdx.x * 128, n0 = blockIdx.y * 128;

    float c[4][4][4];
#pragma unroll
    for (int mt = 0; mt < 4; mt++)
#pragma unroll
        for (int nt = 0; nt < 4; nt++)
#pragma unroll
            for (int i = 0; i < 4; i++) c[mt][nt][i] = 0.f;

    int am = tid >> 1, ak = (tid & 1) * 8;
    bool aval = (m0 + am) < MROWS;
    const float* Ap = A + (size_t)(m0 + am) * DIM + ak;
    int bk = tid >> 4, bn = (tid & 15) * 4;
    const float* Bp = W + (size_t)bk * DIM + n0 + bn;

    const float4 z4 = make_float4(0.f, 0.f, 0.f, 0.f);
    float4 ra0, ra1, rb0, rb1;
    ra0 = aval ? *(const float4*)(Ap)     : z4;
    ra1 = aval ? *(const float4*)(Ap + 4) : z4;
    rb0 = *(const float4*)(Bp);
    rb1 = *(const float4*)(Bp + 64);

    for (int t = 0; t < 64; t++) {
        __syncthreads();
        *(float4*)&As[am][ak] =
            make_float4(to_tf32(ra0.x), to_tf32(ra0.y), to_tf32(ra0.z), to_tf32(ra0.w));
        *(float4*)&As[am][ak + 4] =
            make_float4(to_tf32(ra1.x), to_tf32(ra1.y), to_tf32(ra1.z), to_tf32(ra1.w));
        *(float4*)&Bs[bk][bn] =
            make_float4(to_tf32(rb0.x), to_tf32(rb0.y), to_tf32(rb0.z), to_tf32(rb0.w));
        *(float4*)&Bs[bk][bn + 64] =
            make_float4(to_tf32(rb1.x), to_tf32(rb1.y), to_tf32(rb1.z), to_tf32(rb1.w));
        __syncthreads();

        if (t < 63) {
            const float* Ap2 = Ap + (t + 1) * 16;
            ra0 = aval ? *(const float4*)(Ap2)     : z4;
            ra1 = aval ? *(const float4*)(Ap2 + 4) : z4;
            const float* Bp2 = Bp + (size_t)(t + 1) * 16 * DIM;
            rb0 = *(const float4*)(Bp2);
            rb1 = *(const float4*)(Bp2 + 64);
        }

#pragma unroll
        for (int ks = 0; ks < 2; ks++) {
            int kk = ks * 8;
            unsigned bf[4][2];
#pragma unroll
            for (int nt = 0; nt < 4; nt++) {
                int col = wn * 32 + nt * 8 + lr;
                bf[nt][0] = fu(Bs[kk + lc][col]);
                bf[nt][1] = fu(Bs[kk + lc + 4][col]);
            }
#pragma unroll
            for (int mt = 0; mt < 4; mt++) {
                int ar = wm * 64 + mt * 16 + lr;
                unsigned a0 = fu(As[ar][kk + lc]);
                unsigned a1 = fu(As[ar + 8][kk + lc]);
                unsigned a2 = fu(As[ar][kk + lc + 4]);
                unsigned a3 = fu(As[ar + 8][kk + lc + 4]);
#pragma unroll
                for (int nt = 0; nt < 4; nt++)
                    mma_tf32(c[mt][nt], a0, a1, a2, a3, bf[nt][0], bf[nt][1]);
            }
        }
    }

    // Epilogue
#pragma unroll
    for (int mt = 0; mt < 4; mt++) {
        int r0 = m0 + wm * 64 + mt * 16 + lr;
        int r1 = r0 + 8;
#pragma unroll
        for (int nt = 0; nt < 4; nt++) {
            int n = n0 + wn * 32 + nt * 8 + lc * 2;
            float b0v = bias[n], b1v = bias[n + 1];
            store_pair(csel, Cext, r0, n, c[mt][nt][0] + b0v, c[mt][nt][1] + b1v);
            store_pair(csel, Cext, r1, n, c[mt][nt][2] + b0v, c[mt][nt][3] + b1v);
        }
    }
}

// ---------------------------------------------------------------------------
// TF32 flash attention. 64 q-rows x 64 k-cols tiles. 8 warps (4 row-groups x
// 2 col-groups), warp tile 16x32. QK^T and PV via m16n8k8 tf32 MMA; softmax
// in smem by 4-lane row groups with online m/l/alpha stats.
// ---------------------------------------------------------------------------
#define QST 68   // stride for Qs/Ks/Ss (conflict-free row-major frag loads)
#define VST 72   // stride for Vs (conflict-free col-frag loads)

__global__ __launch_bounds__(256) void attn_tf32()
{
    extern __shared__ float sm[];
    float* Qs  = sm;                 // [64][68]  (pre-scaled by 1/8, tf32)
    float* Ks  = Qs + 64 * QST;      // [64][68]
    float* Ss  = Ks + 64 * QST;      // [64][68]  S then P (tf32)
    float* Vs  = Ss + 64 * QST;      // [64][72]
    float* m_s  = Vs + 64 * VST;     // [64]
    float* l_s  = m_s + 64;          // [64]
    float* al_s = l_s + 64;          // [64]

    int tid = threadIdx.x;
    int wid = tid >> 5, lane = tid & 31;
    int wm = wid & 3;      // row group: rows wm*16 .. +16
    int wn = wid >> 2;     // col group: cols wn*32 .. +32
    int lr = lane >> 2, lc = lane & 3;

    int bh = blockIdx.y;
    int b = bh >> 4;
    int h = bh & 15;
    int q0 = blockIdx.x * 64;

    const float* Qg = g_q + ((size_t)(b * HEADS + h)) * SEQ * HDIM;
    const float* Kg = g_k + ((size_t)(b * HEADS + h)) * SEQ * HDIM;
    const float* Vg = g_v + ((size_t)(b * HEADS + h)) * SEQ * HDIM;

    const float4 z4 = make_float4(0.f, 0.f, 0.f, 0.f);

    // Load Q tile (scaled by 1/sqrt(Dh)=0.125, tf32-rounded)
    for (int e = tid; e < 64 * 16; e += 256) {
        int r = e >> 4;
        int d4 = (e & 15) * 4;
        float4 v = (q0 + r < SEQ) ? *(const float4*)(Qg + (size_t)(q0 + r) * HDIM + d4) : z4;
        *(float4*)&Qs[r * QST + d4] = make_float4(
            to_tf32(v.x * 0.125f), to_tf32(v.y * 0.125f),
            to_tf32(v.z * 0.125f), to_tf32(v.w * 0.125f));
    }
    if (tid < 64) { m_s[tid] = -INFINITY; l_s[tid] = 0.f; }

    float o[4][4];
#pragma unroll
    for (int nt = 0; nt < 4; nt++)
#pragma unroll
        for (int i = 0; i < 4; i++) o[nt][i] = 0.f;

    for (int k0 = 0; k0 < SEQ; k0 += 64) {
        __syncthreads();  // prev iter done with Ks/Vs/Ss
        for (int e = tid; e < 64 * 16; e += 256) {
            int r = e >> 4;
            int d4 = (e & 15) * 4;
            float4 kv = z4, vv = z4;
            if (k0 + r < SEQ) {
                kv = *(const float4*)(Kg + (size_t)(k0 + r) * HDIM + d4);
                vv = *(const float4*)(Vg + (size_t)(k0 + r) * HDIM + d4);
            }
            *(float4*)&Ks[r * QST + d4] = make_float4(
                to_tf32(kv.x), to_tf32(kv.y), to_tf32(kv.z), to_tf32(kv.w));
            *(float4*)&Vs[r * VST + d4] = make_float4(
                to_tf32(vv.x), to_tf32(vv.y), to_tf32(vv.z), to_tf32(vv.w));
        }
        __syncthreads();

        // S = (Q*scale) @ K^T
        float s[4][4];
#pragma unroll
        for (int nt = 0; nt < 4; nt++)
#pragma unroll
            for (int i = 0; i < 4; i++) s[nt][i] = 0.f;

#pragma unroll
        for (int ks = 0; ks < 8; ks++) {
            int kk = ks * 8;
            int qr = wm * 16 + lr;
            unsigned a0 = fu(Qs[qr * QST + kk + lc]);
            unsigned a1 = fu(Qs[(qr + 8) * QST + kk + lc]);
            unsigned a2 = fu(Qs[qr * QST + kk + lc + 4]);
            unsigned a3 = fu(Qs[(qr + 8) * QST + kk + lc + 4]);
#pragma unroll
            for (int nt = 0; nt < 4; nt++) {
                int krow = wn * 32 + nt * 8 + lr;
                unsigned b0 = fu(Ks[krow * QST + kk + lc]);
                unsigned b1 = fu(Ks[krow * QST + kk + lc + 4]);
                mma_tf32(s[nt], a0, a1, a2, a3, b0, b1);
            }
        }

        // Store S fragments to smem
#pragma unroll
        for (int nt = 0; nt < 4; nt++) {
            int cbase = wn * 32 + nt * 8 + lc * 2;
            *(float2*)&Ss[(wm * 16 + lr) * QST + cbase]     = make_float2(s[nt][0], s[nt][1]);
            *(float2*)&Ss[(wm * 16 + lr + 8) * QST + cbase] = make_float2(s[nt][2], s[nt][3]);
        }
        __syncthreads();

        // Softmax: 4 threads per row, 16 cols each; online m/l update.
        {
            int row = tid >> 2, quad = tid & 3;
            float* Sr = &Ss[row * QST + quad * 16];
            float v[16];
            *(float4*)&v[0]  = *(float4*)&Sr[0];
            *(float4*)&v[4]  = *(float4*)&Sr[4];
            *(float4*)&v[8]  = *(float4*)&Sr[8];
            *(float4*)&v[12] = *(float4*)&Sr[12];
            int cb = k0 + quad * 16;
            float rmax = -INFINITY;
#pragma unroll
            for (int i = 0; i < 16; i++) {
                if (cb + i >= SEQ) v[i] = -INFINITY;
                rmax = fmaxf(rmax, v[i]);
            }
            rmax = fmaxf(rmax, __shfl_xor_sync(0xffffffffu, rmax, 1, 4));
            rmax = fmaxf(rmax, __shfl_xor_sync(0xffffffffu, rmax, 2, 4));

            float mold = m_s[row];
            float mn = fmaxf(mold, rmax);
            float alpha = __expf(mold - mn);
            float rsum = 0.f;
#pragma unroll
            for (int i = 0; i < 16; i++) {
                float p = (cb + i < SEQ) ? __expf(v[i] - mn) : 0.f;
                rsum += p;
                v[i] = to_tf32(p);
            }
            rsum += __shfl_xor_sync(0xffffffffu, rsum, 1, 4);
            rsum += __shfl_xor_sync(0xffffffffu, rsum, 2, 4);
            if (quad == 0) {
                m_s[row] = mn;
                l_s[row] = l_s[row] * alpha + rsum;
                al_s[row] = alpha;
            }
            *(float4*)&Sr[0]  = *(float4*)&v[0];
            *(float4*)&Sr[4]  = *(float4*)&v[4];
            *(float4*)&Sr[8]  = *(float4*)&v[8];
            *(float4*)&Sr[12] = *(float4*)&v[12];
        }
        __syncthreads();

        // Rescale O by alpha, then O += P @ V
        {
            int r0 = wm * 16 + lr;
            float a0v = al_s[r0], a1v = al_s[r0 + 8];
#pragma unroll
            for (int nt = 0; nt < 4; nt++) {
                o[nt][0] *= a0v; o[nt][1] *= a0v;
                o[nt][2] *= a1v; o[nt][3] *= a1v;
            }
        }
#pragma unroll
        for (int ks = 0; ks < 8; ks++) {
            int kk = ks * 8;
            int pr = wm * 16 + lr;
            unsigned a0 = fu(Ss[pr * QST + kk + lc]);
            unsigned a1 = fu(Ss[(pr + 8) * QST + kk + lc]);
            unsigned a2 = fu(Ss[pr * QST + kk + lc + 4]);
            unsigned a3 = fu(Ss[(pr + 8) * QST + kk + lc + 4]);
#pragma unroll
            for (int nt = 0; nt < 4; nt++) {
                int vc = wn * 32 + nt * 8 + lr;
                unsigned b0 = fu(Vs[(kk + lc) * VST + vc]);
                unsigned b1 = fu(Vs[(kk + lc + 4) * VST + vc]);
                mma_tf32(o[nt], a0, a1, a2, a3, b0, b1);
            }
        }
    }

    // Epilogue: normalize, write [B,S,D]
    {
        int r0 = wm * 16 + lr, r1 = r0 + 8;
        float inv0 = 1.f / l_s[r0];
        float inv1 = 1.f / l_s[r1];
#pragma unroll
        for (int nt = 0; nt < 4; nt++) {
            int col = h * HDIM + wn * 32 + nt * 8 + lc * 2;
            if (q0 + r0 < SEQ)
                *(float2*)&g_ctx[((size_t)(b * SEQ + q0 + r0)) * DIM + col] =
                    make_float2(o[nt][0] * inv0, o[nt][1] * inv0);
            if (q0 + r1 < SEQ)
                *(float2*)&g_ctx[((size_t)(b * SEQ + q0 + r1)) * DIM + col] =
                    make_float2(o[nt][2] * inv1, o[nt][3] * inv1);
        }
    }
}

// ---------------------------------------------------------------------------
extern "C" void kernel_launch(void* const* d_in, const int* in_sizes, int n_in,
                              void* d_out, int out_size)
{
    const float* x  = (const float*)d_in[0];
    const float* Wq = (const float*)d_in[1];
    const float* bq = (const float*)d_in[2];
    const float* Wk = (const float*)d_in[3];
    const float* bk = (const float*)d_in[4];
    const float* Wv = (const float*)d_in[5];
    const float* bv = (const float*)d_in[6];
    const float* Wo = (const float*)d_in[7];
    const float* bo = (const float*)d_in[8];
    float* out = (float*)d_out;

    dim3 gemmGrid((MROWS + 127) / 128, DIM / 128);  // 86 x 8

    gemm_tf32<<<gemmGrid, 256>>>(x, Wq, bq, nullptr, 0, 0);
    gemm_tf32<<<gemmGrid, 256>>>(x, Wk, bk, nullptr, 0, 1);
    gemm_tf32<<<gemmGrid, 256>>>(x, Wv, bv, nullptr, 0, 2);

    int smem = (3 * 64 * QST + 64 * VST + 3 * 64) * sizeof(float);  // 71424
    cudaFuncSetAttribute(attn_tf32, cudaFuncAttributeMaxDynamicSharedMemorySize, smem);
    dim3 attnGrid((SEQ + 63) / 64, BATCH * HEADS);  // 22 x 128
    attn_tf32<<<attnGrid, 256, smem>>>();

    gemm_tf32<<<gemmGrid, 256>>>(nullptr, Wo, bo, out, 1, 3);
}